// round 13
// baseline (speedup 1.0000x reference)
#include <cuda_runtime.h>
#include <math.h>

// ---------------- problem constants ----------------
#define NP 2048        // pairs
#define NN 4096        // X/Y rows
#define DF 256         // latent dim
#define DX 768         // X dim
#define DY 512         // Y dim
#define CLAMPF 1e-8f
#define EPS_INV 20.0f  // 1/0.05

// ---------------- static device scratch ----------------
__device__ alignas(16) float g_Xa[NN*DX];
__device__ alignas(16) float g_Ya[NN*DY];
__device__ alignas(16) float g_Sxx[DX*DX];
__device__ alignas(16) float g_Syy[DY*DY];
__device__ alignas(16) float g_Sxy[DX*DY];
__device__ alignas(16) float g_fXp[NP*DF];
__device__ alignas(16) float g_fYp[NP*DF];
__device__ alignas(16) float g_Mp[(size_t)NP*NP];
__device__ alignas(16) float g_fXn[NN*DF];
__device__ alignas(16) float g_fYn[NN*DF];
__device__ alignas(16) float g_Mu[(size_t)NN*NN];
__device__ alignas(16) float g_Ma[(size_t)NN*NN];
__device__ alignas(16) float g_P [(size_t)NN*NN];
__device__ alignas(16) float g_XS[NN*DX];   // X@Sxx, later reused as diag(a)*Xu
__device__ alignas(16) float g_YS[NN*DY];   // Y@Syy, later reused as diag(b)*Yu
__device__ alignas(16) float g_Xn[NN*DX];
__device__ alignas(16) float g_Yn[NN*DY];
__device__ alignas(16) float g_Xu[NN*DX];
__device__ alignas(16) float g_Yu[NN*DY];
__device__ alignas(16) float g_T [NN*DY];   // Xn@Sxy, later reused as P@Yu
__device__ alignas(16) float g_Cxx[DX*DX];
__device__ alignas(16) float g_Cyy[DY*DY];
__device__ alignas(16) float g_U1[DX*DY];
__device__ alignas(16) float g_V1[DX*DY];
__device__ alignas(16) float g_Fxx[DF*DF];
__device__ alignas(16) float g_Fyy[DF*DF];
__device__ alignas(16) float g_W1[DX*DF];
__device__ alignas(16) float g_W2[DF*DY];
__device__ alignas(16) float g_W3[DX*DY];
__device__ alignas(16) float g_MA[DX*DX];   // MAx, then MAy, then G (sequential reuse)
__device__ alignas(16) float g_skw[8*DX*DX];// split-K workspace (max: S=8 of 768x768)
__device__ alignas(16) float g_u1[NP];
__device__ alignas(16) float g_v1[NP];      // sinkhorn pairs
__device__ alignas(16) float g_u2[NN];
__device__ alignas(16) float g_v2[NN];      // sinkhorn latent
__device__ alignas(16) float g_u3[NN];
__device__ alignas(16) float g_v3[NN];      // sinkhorn anchor
__device__ alignas(16) float g_ps[128*NN];  // col partials (128 splits max)
__device__ alignas(16) float g_rsp[NP];
__device__ alignas(16) float g_csp[NP];     // plan_p marginals
__device__ alignas(16) float g_a[NN];
__device__ alignas(16) float g_b[NN];       // plan_u marginals
__device__ double g_acc[16];

// acc slots:
// 0: L_marg  1: sail-sum  2: exp-diag-sum  3: imp-diag-logp-sum
// 4: L_ot    5: norm1     6: norm2         7: dot
// 8: frob(MAx) 9: frob(MAy) 10: frob(G)

// ---------------- packed dual-fp32 FMA helpers (sm_103a) ----------------
__device__ __forceinline__ unsigned long long splat2(float x) {
    unsigned long long r;
    asm("mov.b64 %0, {%1, %1};" : "=l"(r) : "f"(x));
    return r;
}
__device__ __forceinline__ void ffma2l(unsigned long long& d, unsigned long long a,
                                       unsigned long long b) {
    asm("fma.rn.f32x2 %0, %1, %2, %0;" : "+l"(d) : "l"(a), "l"(b));
}
__device__ __forceinline__ float2 unpack2(unsigned long long x) {
    float2 r;
    asm("mov.b64 {%0, %1}, %2;" : "=f"(r.x), "=f"(r.y) : "l"(x));
    return r;
}

// ---------------- reduction helpers ----------------
__device__ __forceinline__ float blockReduceSum(float v) {
    __shared__ float sh[32];
    __syncthreads();                       // protect prior use of sh
    int lane = threadIdx.x & 31, wid = threadIdx.x >> 5;
    #pragma unroll
    for (int o = 16; o > 0; o >>= 1) v += __shfl_down_sync(0xffffffffu, v, o);
    if (lane == 0) sh[wid] = v;
    __syncthreads();
    int nw = blockDim.x >> 5;
    v = (threadIdx.x < nw) ? sh[threadIdx.x] : 0.f;
    if (wid == 0) {
        #pragma unroll
        for (int o = 16; o > 0; o >>= 1) v += __shfl_down_sync(0xffffffffu, v, o);
    }
    return v;  // valid on thread 0
}

// broadcast variant: every thread gets the total
__device__ __forceinline__ float blockReduceSumB(float v) {
    __shared__ float sh[32];
    __shared__ float tot;
    __syncthreads();
    int lane = threadIdx.x & 31, wid = threadIdx.x >> 5;
    #pragma unroll
    for (int o = 16; o > 0; o >>= 1) v += __shfl_down_sync(0xffffffffu, v, o);
    if (lane == 0) sh[wid] = v;
    __syncthreads();
    int nw = blockDim.x >> 5;
    v = (threadIdx.x < nw) ? sh[threadIdx.x] : 0.f;
    if (wid == 0) {
        #pragma unroll
        for (int o = 16; o > 0; o >>= 1) v += __shfl_down_sync(0xffffffffu, v, o);
        if (lane == 0) tot = v;
    }
    __syncthreads();
    return tot;
}

// ---------------- elementwise / norms ----------------
__global__ void k_zero_acc() { if (threadIdx.x < 16) g_acc[threadIdx.x] = 0.0; }

__global__ void k_zero_vec(float* v, int n) {
    int i = blockIdx.x * blockDim.x + threadIdx.x;
    if (i < n) v[i] = 0.f;
}

__global__ void k_rownorm(const float* __restrict__ in, float* __restrict__ out, int cols) {
    int row = blockIdx.x;
    const float* r = in + (size_t)row * cols;
    float ss = 0.f;
    for (int c = threadIdx.x; c < cols; c += blockDim.x) { float x = r[c]; ss += x * x; }
    float tot = blockReduceSum(ss);
    __shared__ float sInv;
    if (threadIdx.x == 0) sInv = 1.f / fmaxf(sqrtf(tot), CLAMPF);
    __syncthreads();
    float inv = sInv;
    float* o = out + (size_t)row * cols;
    for (int c = threadIdx.x; c < cols; c += blockDim.x) o[c] = r[c] * inv;
}

// Xn = X / clamp(sqrt(rowdot(X, XS)))
__global__ void k_metricnorm(const float* __restrict__ X, const float* __restrict__ XS,
                             float* __restrict__ Xn, int cols) {
    int row = blockIdx.x;
    const float* r  = X  + (size_t)row * cols;
    const float* rs = XS + (size_t)row * cols;
    float ss = 0.f;
    for (int c = threadIdx.x; c < cols; c += blockDim.x) ss += r[c] * rs[c];
    float tot = blockReduceSum(ss);
    __shared__ float sInv;
    if (threadIdx.x == 0) sInv = 1.f / fmaxf(sqrtf(tot), CLAMPF);
    __syncthreads();
    float inv = sInv;
    float* o = Xn + (size_t)row * cols;
    for (int c = threadIdx.x; c < cols; c += blockDim.x) o[c] = r[c] * inv;
}

__global__ void k_rowscale(const float* __restrict__ in, const float* __restrict__ s,
                           float* __restrict__ out, int C, size_t n) {
    for (size_t idx = (size_t)blockIdx.x * blockDim.x + threadIdx.x; idx < n;
         idx += (size_t)gridDim.x * blockDim.x) {
        int i = (int)(idx / C);
        out[idx] = in[idx] * s[i];
    }
}

// ---------------- GEMM: C = alpha * op(A) @ op(B) ----------------
// logical A is MxK: TA ? stored KxM : stored MxK (row-major)
// logical B is KxN: TB ? stored NxK : stored KxN
// M,N multiples of 128; K multiple of 8. gridDim.z = split-K factor.
// Double-buffered SMEM, register-staged prefetch, 1 sync per k-tile.
// Inner loop: fma.rn.f32x2 with u64 accumulators (in-place, no repacking).
// Accumulator acc[ip][j] holds rows (2ip, 2ip+1) of column j.
template<bool TA, bool TB>
__global__ void __launch_bounds__(256, 2)
k_gemm(const float* __restrict__ A, const float* __restrict__ B,
       float* __restrict__ C, int M, int N, int K, int Kc, float alpha) {
    __shared__ alignas(16) float As[2][8][132];
    __shared__ alignas(16) float Bs[2][8][132];
    int bm = blockIdx.y * 128, bn = blockIdx.x * 128;
    int kb = blockIdx.z * Kc;
    C += (size_t)blockIdx.z * M * N;
    int tid = threadIdx.x;
    int tx = tid & 15, ty = tid >> 4;   // 16x16 threads

    unsigned long long acc[4][8];
    #pragma unroll
    for (int ip = 0; ip < 4; ip++)
        #pragma unroll
        for (int j = 0; j < 8; j++) acc[ip][j] = 0ull;

    float sA[4];     // staging (scalar path)
    float4 sA4;      // staging (vector path)
    float sB[4];
    float4 sB4;

    auto loadA = [&](int k0) {
        if (!TA) {
            int k = tid & 7, m0 = tid >> 3;
            #pragma unroll
            for (int r = 0; r < 4; r++)
                sA[r] = A[(size_t)(bm + m0 + r * 32) * K + (k0 + k)];
        } else {
            int k = tid >> 5, m4 = (tid & 31) * 4;
            sA4 = *reinterpret_cast<const float4*>(&A[(size_t)(k0 + k) * M + bm + m4]);
        }
    };
    auto storeA = [&](int b) {
        if (!TA) {
            int k = tid & 7, m0 = tid >> 3;
            #pragma unroll
            for (int r = 0; r < 4; r++) As[b][k][m0 + r * 32] = sA[r];
        } else {
            int k = tid >> 5, m4 = (tid & 31) * 4;
            *reinterpret_cast<float4*>(&As[b][k][m4]) = sA4;
        }
    };
    auto loadB = [&](int k0) {
        if (!TB) {
            int k = tid >> 5, n4 = (tid & 31) * 4;
            sB4 = *reinterpret_cast<const float4*>(&B[(size_t)(k0 + k) * N + bn + n4]);
        } else {
            int k = tid & 7, n0 = tid >> 3;
            #pragma unroll
            for (int r = 0; r < 4; r++)
                sB[r] = B[(size_t)(bn + n0 + r * 32) * K + (k0 + k)];
        }
    };
    auto storeB = [&](int b) {
        if (!TB) {
            int k = tid >> 5, n4 = (tid & 31) * 4;
            *reinterpret_cast<float4*>(&Bs[b][k][n4]) = sB4;
        } else {
            int k = tid & 7, n0 = tid >> 3;
            #pragma unroll
            for (int r = 0; r < 4; r++) Bs[b][k][n0 + r * 32] = sB[r];
        }
    };

    loadA(kb); loadB(kb);
    storeA(0); storeB(0);
    __syncthreads();
    int buf = 0;
    for (int k0 = kb; k0 < kb + Kc; k0 += 8) {
        bool more = (k0 + 8 < kb + Kc);
        if (more) { loadA(k0 + 8); loadB(k0 + 8); }
        #pragma unroll
        for (int k = 0; k < 8; k++) {
            // A fragment as row-pairs (u64, no packing needed)
            const ulonglong2* apl = reinterpret_cast<const ulonglong2*>(&As[buf][k][ty * 8]);
            ulonglong2 A0 = apl[0], A1 = apl[1];
            unsigned long long ap[4] = {A0.x, A0.y, A1.x, A1.y};
            // B fragment as scalars -> splats
            const float4* bp = reinterpret_cast<const float4*>(&Bs[buf][k][tx * 8]);
            float4 b0 = bp[0], b1 = bp[1];
            unsigned long long bsp[8] = {
                splat2(b0.x), splat2(b0.y), splat2(b0.z), splat2(b0.w),
                splat2(b1.x), splat2(b1.y), splat2(b1.z), splat2(b1.w)};
            #pragma unroll
            for (int ip = 0; ip < 4; ip++)
                #pragma unroll
                for (int j = 0; j < 8; j++)
                    ffma2l(acc[ip][j], ap[ip], bsp[j]);
        }
        if (more) {
            storeA(buf ^ 1); storeB(buf ^ 1);
            __syncthreads();
            buf ^= 1;
        }
    }
    #pragma unroll
    for (int ip = 0; ip < 4; ip++) {
        float c0[8], c1[8];
        #pragma unroll
        for (int j = 0; j < 8; j++) {
            float2 p = unpack2(acc[ip][j]);
            c0[j] = alpha * p.x;
            c1[j] = alpha * p.y;
        }
        int gm0 = bm + ty * 8 + 2 * ip;
        float* cp0 = &C[(size_t)gm0 * N + bn + tx * 8];
        float* cp1 = &C[(size_t)(gm0 + 1) * N + bn + tx * 8];
        reinterpret_cast<float4*>(cp0)[0] = make_float4(c0[0], c0[1], c0[2], c0[3]);
        reinterpret_cast<float4*>(cp0)[1] = make_float4(c0[4], c0[5], c0[6], c0[7]);
        reinterpret_cast<float4*>(cp1)[0] = make_float4(c1[0], c1[1], c1[2], c1[3]);
        reinterpret_cast<float4*>(cp1)[1] = make_float4(c1[4], c1[5], c1[6], c1[7]);
    }
}

// Sum S slices of the split-K workspace into C (deterministic order).
__global__ void k_sk_reduce(const float* __restrict__ W, float* __restrict__ C,
                            size_t mn, int S) {
    for (size_t i = (size_t)blockIdx.x * blockDim.x + threadIdx.x; i < mn;
         i += (size_t)gridDim.x * blockDim.x) {
        float s = 0.f;
        for (int k = 0; k < S; k++) s += W[(size_t)k * mn + i];
        C[i] = s;
    }
}

// ---------------- Sinkhorn (fused row+col pass, one M read per iteration) ----
// M in [-20,20]; u,v bounded -> plain exp safe in fp32.
// e = exp(M + v_old); row LSE gives u_new; col partial accumulates e*exp(u_new)
//   = exp(v_old[col]) * exp(M + u_new), corrected in the combine:
// v_new = log_b + v_old - log(sum ps).
template<int CPT>
__global__ void k_sink_iter(const float* __restrict__ M, const float* __restrict__ v,
                            float* __restrict__ u, float* __restrict__ ps,
                            int C, int RB, float log_a) {
    int t = threadIdx.x;
    int r0 = blockIdx.y * RB;
    float vv[CPT], part[CPT];
    #pragma unroll
    for (int k = 0; k < CPT; k++) { vv[k] = v[t + (k << 8)]; part[k] = 0.f; }
    for (int r = r0; r < r0 + RB; r++) {
        const float* row = M + (size_t)r * C;
        float e[CPT];
        float s = 0.f;
        #pragma unroll
        for (int k = 0; k < CPT; k++) {
            e[k] = __expf(row[t + (k << 8)] + vv[k]);
            s += e[k];
        }
        float S = blockReduceSumB(s);
        float ur = log_a - logf(S);
        if (t == 0) u[r] = ur;
        float eu = __expf(ur);
        #pragma unroll
        for (int k = 0; k < CPT; k++) part[k] += e[k] * eu;
    }
    #pragma unroll
    for (int k = 0; k < CPT; k++) ps[(size_t)blockIdx.y * C + t + (k << 8)] = part[k];
}

__global__ void k_sink_comb(const float* __restrict__ ps, float* __restrict__ v,
                            int C, int splits, float log_b) {
    int col = blockIdx.x * blockDim.x + threadIdx.x;
    if (col >= C) return;
    float s = 0.f;
    for (int k = 0; k < splits; k++) s += ps[(size_t)k * C + col];
    v[col] = log_b + v[col] - logf(s);
}

// fused plan_p marginals: row sums (rs) + col partials (ps) of exp(M+u+v), one read
template<int CPT>
__global__ void k_pp_marg(const float* __restrict__ M, const float* __restrict__ u,
                          const float* __restrict__ v, float* __restrict__ rs,
                          float* __restrict__ ps, int C, int RB) {
    int t = threadIdx.x;
    int r0 = blockIdx.y * RB;
    float vv[CPT], part[CPT];
    #pragma unroll
    for (int k = 0; k < CPT; k++) { vv[k] = v[t + (k << 8)]; part[k] = 0.f; }
    for (int r = r0; r < r0 + RB; r++) {
        const float* row = M + (size_t)r * C;
        float uu = u[r];
        float e[CPT];
        float s = 0.f;
        #pragma unroll
        for (int k = 0; k < CPT; k++) {
            e[k] = __expf(row[t + (k << 8)] + uu + vv[k]);
            s += e[k];
        }
        float S = blockReduceSumB(s);
        if (t == 0) rs[r] = S;
        #pragma unroll
        for (int k = 0; k < CPT; k++) part[k] += e[k];
    }
    #pragma unroll
    for (int k = 0; k < CPT; k++) ps[(size_t)blockIdx.y * C + t + (k << 8)] = part[k];
}

// fused plan_u: write P = exp(M+u+v), row sums, col partials — one read, one write
template<int CPT>
__global__ void k_plan_marg(const float* __restrict__ M, const float* __restrict__ u,
                            const float* __restrict__ v, float* __restrict__ P,
                            float* __restrict__ rs, float* __restrict__ ps,
                            int C, int RB) {
    int t = threadIdx.x;
    int r0 = blockIdx.y * RB;
    float vv[CPT], part[CPT];
    #pragma unroll
    for (int k = 0; k < CPT; k++) { vv[k] = v[t + (k << 8)]; part[k] = 0.f; }
    for (int r = r0; r < r0 + RB; r++) {
        const float* row = M + (size_t)r * C;
        float* prow = P + (size_t)r * C;
        float uu = u[r];
        float e[CPT];
        float s = 0.f;
        #pragma unroll
        for (int k = 0; k < CPT; k++) {
            e[k] = __expf(row[t + (k << 8)] + uu + vv[k]);
            prow[t + (k << 8)] = e[k];
            s += e[k];
        }
        float S = blockReduceSumB(s);
        if (t == 0) rs[r] = S;
        #pragma unroll
        for (int k = 0; k < CPT; k++) part[k] += e[k];
    }
    #pragma unroll
    for (int k = 0; k < CPT; k++) ps[(size_t)blockIdx.y * C + t + (k << 8)] = part[k];
}

__global__ void k_colsum_comb(const float* __restrict__ part, float* __restrict__ cs,
                              int C, int splits) {
    int col = blockIdx.x * blockDim.x + threadIdx.x;
    if (col >= C) return;
    float s = 0.f;
    for (int k = 0; k < splits; k++) s += part[(size_t)k * C + col];
    cs[col] = s;
}

// ---------------- loss reductions ----------------
__global__ void k_marg(const float* __restrict__ s, int n) {
    float inv = 1.f / (float)n;
    float local = 0.f;
    for (int i = blockIdx.x * blockDim.x + threadIdx.x; i < n; i += gridDim.x * blockDim.x) {
        float d = s[i] - inv; local += d * d;
    }
    float tot = blockReduceSum(local);
    if (threadIdx.x == 0) atomicAdd(&g_acc[0], (double)tot);
}

// sail / exp / imp over the pair cost matrix
__global__ void k_pair_losses(const float* __restrict__ Mp, const float* __restrict__ u,
                              const float* __restrict__ v) {
    float sail = 0.f, expd = 0.f, impd = 0.f;
    const size_t n = (size_t)NP * NP;
    for (size_t idx = (size_t)blockIdx.x * blockDim.x + threadIdx.x; idx < n;
         idx += (size_t)gridDim.x * blockDim.x) {
        int i = (int)(idx >> 11), j = (int)(idx & 2047);
        float mval = Mp[idx];
        float cosv = mval * 0.05f;                 // Mp = 20*cos
        float z = (i == j) ? cosv * 10.f : -cosv * 10.f;
        float x = -z;                              // softplus(-z) = -log_sigmoid(z)
        float sp = (x > 0.f) ? x + log1pf(__expf(-x)) : log1pf(__expf(x));
        sail += sp;
        if (i == j) {
            expd += (1.f - cosv) * 0.5f;
            impd += mval + u[i] + v[j];
        }
    }
    float t;
    t = blockReduceSum(sail); if (threadIdx.x == 0) atomicAdd(&g_acc[1], (double)t);
    t = blockReduceSum(expd); if (threadIdx.x == 0) atomicAdd(&g_acc[2], (double)t);
    t = blockReduceSum(impd); if (threadIdx.x == 0) atomicAdd(&g_acc[3], (double)t);
}

// L_ot = sum( exp(logp_a) * (logp_a - logp_u) )
__global__ void k_ot(const float* __restrict__ Ma, const float* __restrict__ ua,
                     const float* __restrict__ va, const float* __restrict__ Mu,
                     const float* __restrict__ uu, const float* __restrict__ vu) {
    float local = 0.f;
    const size_t n = (size_t)NN * NN;
    for (size_t idx = (size_t)blockIdx.x * blockDim.x + threadIdx.x; idx < n;
         idx += (size_t)gridDim.x * blockDim.x) {
        int i = (int)(idx >> 12), j = (int)(idx & 4095);
        float lpa = Ma[idx] + ua[i] + va[j];
        float lpu = Mu[idx] + uu[i] + vu[j];
        local += __expf(lpa) * (lpa - lpu);
    }
    float tot = blockReduceSum(local);
    if (threadIdx.x == 0) atomicAdd(&g_acc[4], (double)tot);
}

__global__ void k_dot(const float* __restrict__ A, const float* __restrict__ B,
                      size_t n, int slot) {
    float local = 0.f;
    for (size_t i = (size_t)blockIdx.x * blockDim.x + threadIdx.x; i < n;
         i += (size_t)gridDim.x * blockDim.x) local += A[i] * B[i];
    float tot = blockReduceSum(local);
    if (threadIdx.x == 0) atomicAdd(&g_acc[slot], (double)tot);
}

__global__ void k_final(float* out) {
    double Npd = 2048.0;
    double cste = 4096.0 * 4096.0;
    double L = g_acc[0]
             + g_acc[1] / (Npd * Npd)
             + g_acc[2] / Npd
             + (-(g_acc[3]) / Npd - log(Npd))
             + g_acc[4]
             + (g_acc[5] + g_acc[6] - 2.0 * g_acc[7]) / cste
             + (g_acc[8] + g_acc[9] - 2.0 * g_acc[10]);
    out[0] = (float)L;
}

// ---------------- host-side helpers ----------------
static inline float* sym(const void* s) {
    void* p = nullptr;
    cudaGetSymbolAddress(&p, s);
    return (float*)p;
}

// S = split-K factor (K % S == 0 and (K/S) % 8 == 0 required).
static inline void gemm(const float* A, const float* B, float* C,
                        int M, int N, int K, float alpha, bool ta, bool tb, int S = 1) {
    float* out = C;
    if (S > 1) out = sym(g_skw);
    int Kc = K / S;
    dim3 g(N / 128, M / 128, S), b(256);
    if (!ta && !tb)      k_gemm<false, false><<<g, b>>>(A, B, out, M, N, K, Kc, alpha);
    else if (ta && !tb)  k_gemm<true,  false><<<g, b>>>(A, B, out, M, N, K, Kc, alpha);
    else if (!ta && tb)  k_gemm<false, true ><<<g, b>>>(A, B, out, M, N, K, Kc, alpha);
    else                 k_gemm<true,  true ><<<g, b>>>(A, B, out, M, N, K, Kc, alpha);
    if (S > 1) {
        size_t mn = (size_t)M * N;
        int blocks = (int)((mn + 255) / 256);
        if (blocks > 1024) blocks = 1024;
        k_sk_reduce<<<blocks, 256>>>(out, C, mn, S);
    }
}

// fused Sinkhorn: 2 kernels per iteration, M read once per iteration.
template<int CPT>
static inline void run_sinkhorn(const float* M, float* u, float* v, int R, int C,
                                int RB, float* ps) {
    float log_a = -logf((float)R), log_b = -logf((float)C);
    int splits = R / RB;
    k_zero_vec<<<(C + 255) / 256, 256>>>(v, C);
    for (int it = 0; it < 10; it++) {
        k_sink_iter<CPT><<<dim3(1, splits), 256>>>(M, v, u, ps, C, RB, log_a);
        k_sink_comb<<<(C + 255) / 256, 256>>>(ps, v, C, splits, log_b);
    }
}

extern "C" void kernel_launch(void* const* d_in, const int* in_sizes, int n_in,
                              void* d_out, int out_size) {
    const float* fXp = (const float*)d_in[0];
    const float* fYp = (const float*)d_in[1];
    const float* X   = (const float*)d_in[2];
    const float* Y   = (const float*)d_in[3];
    const float* fX  = (const float*)d_in[4];
    const float* fY  = (const float*)d_in[5];
    const float* Xan = (const float*)d_in[6];
    const float* Yan = (const float*)d_in[7];
    float* out = (float*)d_out;

    float *pXa = sym(g_Xa), *pYa = sym(g_Ya);
    float *pSxx = sym(g_Sxx), *pSyy = sym(g_Syy), *pSxy = sym(g_Sxy);
    float *pfXp = sym(g_fXp), *pfYp = sym(g_fYp);
    float *pMp = sym(g_Mp);
    float *pfXn = sym(g_fXn), *pfYn = sym(g_fYn);
    float *pMu = sym(g_Mu), *pMa = sym(g_Ma), *pP = sym(g_P);
    float *pXS = sym(g_XS), *pYS = sym(g_YS);
    float *pXn = sym(g_Xn), *pYn = sym(g_Yn);
    float *pXu = sym(g_Xu), *pYu = sym(g_Yu);
    float *pT = sym(g_T);
    float *pCxx = sym(g_Cxx), *pCyy = sym(g_Cyy);
    float *pU1 = sym(g_U1), *pV1 = sym(g_V1);
    float *pFxx = sym(g_Fxx), *pFyy = sym(g_Fyy);
    float *pW1 = sym(g_W1), *pW2 = sym(g_W2), *pW3 = sym(g_W3);
    float *pMA = sym(g_MA);
    float *pu1 = sym(g_u1), *pv1 = sym(g_v1);
    float *pu2 = sym(g_u2), *pv2 = sym(g_v2);
    float *pu3 = sym(g_u3), *pv3 = sym(g_v3);
    float *pps = sym(g_ps);
    float *prsp = sym(g_rsp), *pcsp = sym(g_csp);
    float *pa = sym(g_a), *pb = sym(g_b);

    k_zero_acc<<<1, 32>>>();

    // ---- anchor covariances ----
    k_rownorm<<<NN, 256>>>(Xan, pXa, DX);
    k_rownorm<<<NN, 256>>>(Yan, pYa, DY);
    const float invN = 1.0f / (float)NN;
    gemm(pXa, pXa, pSxx, DX, DX, NN, invN, true, false, 8);
    gemm(pYa, pYa, pSyy, DY, DY, NN, invN, true, false, 8);
    gemm(pXa, pYa, pSxy, DX, DY, NN, invN, true, false, 8);

    // ---- cost matrices (M = cos/eps = 20*cos) ----
    k_rownorm<<<NP, 256>>>(fXp, pfXp, DF);
    k_rownorm<<<NP, 256>>>(fYp, pfYp, DF);
    gemm(pfXp, pfYp, pMp, NP, NP, DF, EPS_INV, false, true);
    k_rownorm<<<NN, 256>>>(fX, pfXn, DF);
    k_rownorm<<<NN, 256>>>(fY, pfYn, DF);
    gemm(pfXn, pfYn, pMu, NN, NN, DF, EPS_INV, false, true);

    // ---- sinkhorns (pairs + latent) ----
    run_sinkhorn<8>(pMp, pu1, pv1, NP, NP, 16, pps);    // 128 splits
    run_sinkhorn<16>(pMu, pu2, pv2, NN, NN, 32, pps);   // 128 splits

    // ---- plan_p marginals (fused, single M read) + pair losses ----
    k_pp_marg<8><<<dim3(1, NP / 16), 256>>>(pMp, pu1, pv1, prsp, pps, NP, 16);
    k_colsum_comb<<<(NP + 255) / 256, 256>>>(pps, pcsp, NP, NP / 16);
    k_marg<<<(NP + 255) / 256, 256>>>(prsp, NP);
    k_marg<<<(NP + 255) / 256, 256>>>(pcsp, NP);
    k_pair_losses<<<4096, 256>>>(pMp, pu1, pv1);

    // ---- plan_u: materialize P + marginals in one pass ----
    k_plan_marg<16><<<dim3(1, NN / 32), 256>>>(pMu, pu2, pv2, pP, pa, pps, NN, 32);
    k_colsum_comb<<<(NN + 255) / 256, 256>>>(pps, pb, NN, NN / 32);
    k_marg<<<(NN + 255) / 256, 256>>>(pa, NN);
    k_marg<<<(NN + 255) / 256, 256>>>(pb, NN);

    // ---- anchor-space plan ----
    gemm(X, pSxx, pXS, NN, DX, DX, 1.0f, false, false);           // grid 192
    k_metricnorm<<<NN, 256>>>(X, pXS, pXn, DX);
    gemm(Y, pSyy, pYS, NN, DY, DY, 1.0f, false, false, 2);        // 128 -> 256
    k_metricnorm<<<NN, 256>>>(Y, pYS, pYn, DY);
    gemm(pXn, pSxy, pT, NN, DY, DX, 1.0f, false, false, 2);       // 128 -> 256
    gemm(pT, pYn, pMa, NN, NN, DY, EPS_INV, false, true);         // grid 1024
    run_sinkhorn<16>(pMa, pu3, pv3, NN, NN, 32, pps);
    k_ot<<<4096, 256>>>(pMa, pu3, pv3, pMu, pu2, pv2);

    // ---- L_div ----
    gemm(pXn, pXn, pCxx, DX, DX, NN, 1.0f, true, false, 8);
    gemm(pYn, pYn, pCyy, DY, DY, NN, 1.0f, true, false, 8);
    gemm(pCxx, pSxy, pU1, DX, DY, DX, 1.0f, false, false, 6);     // Kc=128
    gemm(pU1, pCyy, pV1, DX, DY, DY, 1.0f, false, false, 8);      // Kc=64
    k_dot<<<1024, 256>>>(pV1, pSxy, (size_t)DX * DY, 5);
    gemm(pfXn, pfXn, pFxx, DF, DF, NN, 1.0f, true, false, 32);    // 4 -> 128
    gemm(pfYn, pfYn, pFyy, DF, DF, NN, 1.0f, true, false, 32);
    k_dot<<<256, 256>>>(pFxx, pFyy, (size_t)DF * DF, 6);
    gemm(pXn, pfXn, pW1, DX, DF, NN, 1.0f, true, false, 16);      // 12 -> 192
    gemm(pfYn, pYn, pW2, DF, DY, NN, 1.0f, true, false, 16);      // 8 -> 128
    gemm(pW1, pW2, pW3, DX, DY, DF, 1.0f, false, false, 8);       // Kc=32
    k_dot<<<1024, 256>>>(pW3, pSxy, (size_t)DX * DY, 7);

    // ---- L_gw (factored; Kx/Ky never materialized) ----
    k_rownorm<<<NN, 256>>>(X, pXu, DX);
    k_rownorm<<<NN, 256>>>(Y, pYu, DY);
    // aKx^2a = || Xu^T diag(a) Xu ||_F^2
    k_rowscale<<<4096, 256>>>(pXu, pa, pXS, DX, (size_t)NN * DX);
    gemm(pXu, pXS, pMA, DX, DX, NN, 1.0f, true, false, 8);
    k_dot<<<1024, 256>>>(pMA, pMA, (size_t)DX * DX, 8);
    // bKy^2b = || Yu^T diag(b) Yu ||_F^2
    k_rowscale<<<4096, 256>>>(pYu, pb, pYS, DY, (size_t)NN * DY);
    gemm(pYu, pYS, pMA, DY, DY, NN, 1.0f, true, false, 8);
    k_dot<<<1024, 256>>>(pMA, pMA, (size_t)DY * DY, 9);
    // cross term = || Xu^T P Yu ||_F^2
    gemm(pP, pYu, pT, NN, DY, NN, 1.0f, false, false, 2);         // 128 -> 256
    gemm(pXu, pT, pMA, DX, DY, NN, 1.0f, true, false, 8);         // 24 -> 192
    k_dot<<<1024, 256>>>(pMA, pMA, (size_t)DX * DY, 10);

    // ---- combine ----
    k_final<<<1, 1>>>(out);
}

// round 14
// speedup vs baseline: 1.0173x; 1.0173x over previous
#include <cuda_runtime.h>
#include <math.h>

// ---------------- problem constants ----------------
#define NP 2048        // pairs
#define NN 4096        // X/Y rows
#define DF 256         // latent dim
#define DX 768         // X dim
#define DY 512         // Y dim
#define CLAMPF 1e-8f
#define EPS_INV 20.0f  // 1/0.05

// ---------------- static device scratch ----------------
__device__ alignas(16) float g_Xa[NN*DX];
__device__ alignas(16) float g_Ya[NN*DY];
__device__ alignas(16) float g_Sxx[DX*DX];
__device__ alignas(16) float g_Syy[DY*DY];
__device__ alignas(16) float g_Sxy[DX*DY];
__device__ alignas(16) float g_fXp[NP*DF];
__device__ alignas(16) float g_fYp[NP*DF];
__device__ alignas(16) float g_Mp[(size_t)NP*NP];
__device__ alignas(16) float g_fXn[NN*DF];
__device__ alignas(16) float g_fYn[NN*DF];
__device__ alignas(16) float g_Mu[(size_t)NN*NN];
__device__ alignas(16) float g_Ma[(size_t)NN*NN];
__device__ alignas(16) float g_P [(size_t)NN*NN];
__device__ alignas(16) float g_XS[NN*DX];   // X@Sxx, later reused as diag(a)*Xu
__device__ alignas(16) float g_YS[NN*DY];   // Y@Syy, later reused as diag(b)*Yu
__device__ alignas(16) float g_Xn[NN*DX];
__device__ alignas(16) float g_Yn[NN*DY];
__device__ alignas(16) float g_Xu[NN*DX];
__device__ alignas(16) float g_Yu[NN*DY];
__device__ alignas(16) float g_T [NN*DY];   // Xn@Sxy, later reused as P@Yu
__device__ alignas(16) float g_Cxx[DX*DX];
__device__ alignas(16) float g_Cyy[DY*DY];
__device__ alignas(16) float g_U1[DX*DY];
__device__ alignas(16) float g_V1[DX*DY];
__device__ alignas(16) float g_Fxx[DF*DF];
__device__ alignas(16) float g_Fyy[DF*DF];
__device__ alignas(16) float g_W1[DX*DF];
__device__ alignas(16) float g_W2[DF*DY];
__device__ alignas(16) float g_W3[DX*DY];
__device__ alignas(16) float g_MA[DX*DX];   // MAx, then MAy, then G (sequential reuse)
__device__ alignas(16) float g_skw[8*DX*DX];// split-K workspace (max: S=8 of 768x768)
__device__ alignas(16) float g_u1[NP];
__device__ alignas(16) float g_v1[NP];      // sinkhorn pairs
__device__ alignas(16) float g_u2[NN];
__device__ alignas(16) float g_v2[NN];      // sinkhorn latent
__device__ alignas(16) float g_u3[NN];
__device__ alignas(16) float g_v3[NN];      // sinkhorn anchor
__device__ alignas(16) float g_ps[(size_t)512*NN]; // col partials (512 splits max)
__device__ alignas(16) float g_rsp[NP];
__device__ alignas(16) float g_csp[NP];     // plan_p marginals
__device__ alignas(16) float g_a[NN];
__device__ alignas(16) float g_b[NN];       // plan_u marginals
__device__ double g_acc[16];

// acc slots:
// 0: L_marg  1: sail-sum  2: exp-diag-sum  3: imp-diag-logp-sum
// 4: L_ot    5: norm1     6: norm2         7: dot
// 8: frob(MAx) 9: frob(MAy) 10: frob(G)

// ---------------- packed dual-fp32 FMA (sm_103a) ----------------
// float2 variant (R9-measured best GEMM inner loop: 110us on k_gemm<1,0>)
__device__ __forceinline__ float2 ffma2(float2 a, float2 b, float2 c) {
    float2 d;
    asm("{\n\t"
        ".reg .b64 ra, rb, rc, rd;\n\t"
        "mov.b64 ra, {%2, %3};\n\t"
        "mov.b64 rb, {%4, %5};\n\t"
        "mov.b64 rc, {%6, %7};\n\t"
        "fma.rn.f32x2 rd, ra, rb, rc;\n\t"
        "mov.b64 {%0, %1}, rd;\n\t"
        "}"
        : "=f"(d.x), "=f"(d.y)
        : "f"(a.x), "f"(a.y), "f"(b.x), "f"(b.y), "f"(c.x), "f"(c.y));
    return d;
}

// ---------------- reduction helpers ----------------
__device__ __forceinline__ float blockReduceSum(float v) {
    __shared__ float sh[32];
    __syncthreads();                       // protect prior use of sh
    int lane = threadIdx.x & 31, wid = threadIdx.x >> 5;
    #pragma unroll
    for (int o = 16; o > 0; o >>= 1) v += __shfl_down_sync(0xffffffffu, v, o);
    if (lane == 0) sh[wid] = v;
    __syncthreads();
    int nw = blockDim.x >> 5;
    v = (threadIdx.x < nw) ? sh[threadIdx.x] : 0.f;
    if (wid == 0) {
        #pragma unroll
        for (int o = 16; o > 0; o >>= 1) v += __shfl_down_sync(0xffffffffu, v, o);
    }
    return v;  // valid on thread 0
}

// broadcast variant: every thread gets the total
__device__ __forceinline__ float blockReduceSumB(float v) {
    __shared__ float sh[32];
    __shared__ float tot;
    __syncthreads();
    int lane = threadIdx.x & 31, wid = threadIdx.x >> 5;
    #pragma unroll
    for (int o = 16; o > 0; o >>= 1) v += __shfl_down_sync(0xffffffffu, v, o);
    if (lane == 0) sh[wid] = v;
    __syncthreads();
    int nw = blockDim.x >> 5;
    v = (threadIdx.x < nw) ? sh[threadIdx.x] : 0.f;
    if (wid == 0) {
        #pragma unroll
        for (int o = 16; o > 0; o >>= 1) v += __shfl_down_sync(0xffffffffu, v, o);
        if (lane == 0) tot = v;
    }
    __syncthreads();
    return tot;
}

// ---------------- elementwise / norms ----------------
__global__ void k_zero_acc() { if (threadIdx.x < 16) g_acc[threadIdx.x] = 0.0; }

__global__ void k_zero_vec(float* v, int n) {
    int i = blockIdx.x * blockDim.x + threadIdx.x;
    if (i < n) v[i] = 0.f;
}

__global__ void k_rownorm(const float* __restrict__ in, float* __restrict__ out, int cols) {
    int row = blockIdx.x;
    const float* r = in + (size_t)row * cols;
    float ss = 0.f;
    for (int c = threadIdx.x; c < cols; c += blockDim.x) { float x = r[c]; ss += x * x; }
    float tot = blockReduceSum(ss);
    __shared__ float sInv;
    if (threadIdx.x == 0) sInv = 1.f / fmaxf(sqrtf(tot), CLAMPF);
    __syncthreads();
    float inv = sInv;
    float* o = out + (size_t)row * cols;
    for (int c = threadIdx.x; c < cols; c += blockDim.x) o[c] = r[c] * inv;
}

// Xn = X / clamp(sqrt(rowdot(X, XS)))
__global__ void k_metricnorm(const float* __restrict__ X, const float* __restrict__ XS,
                             float* __restrict__ Xn, int cols) {
    int row = blockIdx.x;
    const float* r  = X  + (size_t)row * cols;
    const float* rs = XS + (size_t)row * cols;
    float ss = 0.f;
    for (int c = threadIdx.x; c < cols; c += blockDim.x) ss += r[c] * rs[c];
    float tot = blockReduceSum(ss);
    __shared__ float sInv;
    if (threadIdx.x == 0) sInv = 1.f / fmaxf(sqrtf(tot), CLAMPF);
    __syncthreads();
    float inv = sInv;
    float* o = Xn + (size_t)row * cols;
    for (int c = threadIdx.x; c < cols; c += blockDim.x) o[c] = r[c] * inv;
}

__global__ void k_rowscale(const float* __restrict__ in, const float* __restrict__ s,
                           float* __restrict__ out, int C, size_t n) {
    for (size_t idx = (size_t)blockIdx.x * blockDim.x + threadIdx.x; idx < n;
         idx += (size_t)gridDim.x * blockDim.x) {
        int i = (int)(idx / C);
        out[idx] = in[idx] * s[i];
    }
}

// ---------------- GEMM: C = alpha * op(A) @ op(B) ----------------
// R9-measured best variant: float2 accumulators + ffma2, packed along j.
// logical A is MxK: TA ? stored KxM : stored MxK (row-major)
// logical B is KxN: TB ? stored NxK : stored KxN
// M,N multiples of 128; K multiple of 8. gridDim.z = split-K factor.
template<bool TA, bool TB>
__global__ void __launch_bounds__(256, 2)
k_gemm(const float* __restrict__ A, const float* __restrict__ B,
       float* __restrict__ C, int M, int N, int K, int Kc, float alpha) {
    __shared__ alignas(16) float As[2][8][132];
    __shared__ alignas(16) float Bs[2][8][132];
    int bm = blockIdx.y * 128, bn = blockIdx.x * 128;
    int kb = blockIdx.z * Kc;
    C += (size_t)blockIdx.z * M * N;
    int tid = threadIdx.x;
    int tx = tid & 15, ty = tid >> 4;   // 16x16 threads

    float2 accP[8][4];                  // packed along j: accP[i][jp] = {c(i,2jp), c(i,2jp+1)}
    #pragma unroll
    for (int i = 0; i < 8; i++)
        #pragma unroll
        for (int jp = 0; jp < 4; jp++) accP[i][jp] = make_float2(0.f, 0.f);

    float sA[4];     // staging (scalar path)
    float4 sA4;      // staging (vector path)
    float sB[4];
    float4 sB4;

    auto loadA = [&](int k0) {
        if (!TA) {
            int k = tid & 7, m0 = tid >> 3;
            #pragma unroll
            for (int r = 0; r < 4; r++)
                sA[r] = A[(size_t)(bm + m0 + r * 32) * K + (k0 + k)];
        } else {
            int k = tid >> 5, m4 = (tid & 31) * 4;
            sA4 = *reinterpret_cast<const float4*>(&A[(size_t)(k0 + k) * M + bm + m4]);
        }
    };
    auto storeA = [&](int b) {
        if (!TA) {
            int k = tid & 7, m0 = tid >> 3;
            #pragma unroll
            for (int r = 0; r < 4; r++) As[b][k][m0 + r * 32] = sA[r];
        } else {
            int k = tid >> 5, m4 = (tid & 31) * 4;
            *reinterpret_cast<float4*>(&As[b][k][m4]) = sA4;
        }
    };
    auto loadB = [&](int k0) {
        if (!TB) {
            int k = tid >> 5, n4 = (tid & 31) * 4;
            sB4 = *reinterpret_cast<const float4*>(&B[(size_t)(k0 + k) * N + bn + n4]);
        } else {
            int k = tid & 7, n0 = tid >> 3;
            #pragma unroll
            for (int r = 0; r < 4; r++)
                sB[r] = B[(size_t)(bn + n0 + r * 32) * K + (k0 + k)];
        }
    };
    auto storeB = [&](int b) {
        if (!TB) {
            int k = tid >> 5, n4 = (tid & 31) * 4;
            *reinterpret_cast<float4*>(&Bs[b][k][n4]) = sB4;
        } else {
            int k = tid & 7, n0 = tid >> 3;
            #pragma unroll
            for (int r = 0; r < 4; r++) Bs[b][k][n0 + r * 32] = sB[r];
        }
    };

    loadA(kb); loadB(kb);
    storeA(0); storeB(0);
    __syncthreads();
    int buf = 0;
    for (int k0 = kb; k0 < kb + Kc; k0 += 8) {
        bool more = (k0 + 8 < kb + Kc);
        if (more) { loadA(k0 + 8); loadB(k0 + 8); }
        #pragma unroll
        for (int k = 0; k < 8; k++) {
            const float4* ap = reinterpret_cast<const float4*>(&As[buf][k][ty * 8]);
            const float4* bp = reinterpret_cast<const float4*>(&Bs[buf][k][tx * 8]);
            float4 a0 = ap[0], a1 = ap[1];
            float4 b0 = bp[0], b1 = bp[1];
            float ra[8] = {a0.x, a0.y, a0.z, a0.w, a1.x, a1.y, a1.z, a1.w};
            float2 rbP[4] = {make_float2(b0.x, b0.y), make_float2(b0.z, b0.w),
                             make_float2(b1.x, b1.y), make_float2(b1.z, b1.w)};
            #pragma unroll
            for (int i = 0; i < 8; i++) {
                float2 aa = make_float2(ra[i], ra[i]);
                #pragma unroll
                for (int jp = 0; jp < 4; jp++)
                    accP[i][jp] = ffma2(aa, rbP[jp], accP[i][jp]);
            }
        }
        if (more) {
            storeA(buf ^ 1); storeB(buf ^ 1);
            __syncthreads();
            buf ^= 1;
        }
    }
    #pragma unroll
    for (int i = 0; i < 8; i++) {
        int gm = bm + ty * 8 + i;
        float* cp = &C[(size_t)gm * N + bn + tx * 8];
        float4 o0 = make_float4(alpha * accP[i][0].x, alpha * accP[i][0].y,
                                alpha * accP[i][1].x, alpha * accP[i][1].y);
        float4 o1 = make_float4(alpha * accP[i][2].x, alpha * accP[i][2].y,
                                alpha * accP[i][3].x, alpha * accP[i][3].y);
        reinterpret_cast<float4*>(cp)[0] = o0;
        reinterpret_cast<float4*>(cp)[1] = o1;
    }
}

// Sum S slices of the split-K workspace into C (deterministic order).
__global__ void k_sk_reduce(const float* __restrict__ W, float* __restrict__ C,
                            size_t mn, int S) {
    for (size_t i = (size_t)blockIdx.x * blockDim.x + threadIdx.x; i < mn;
         i += (size_t)gridDim.x * blockDim.x) {
        float s = 0.f;
        for (int k = 0; k < S; k++) s += W[(size_t)k * mn + i];
        C[i] = s;
    }
}

// ---------------- Sinkhorn (fused row+col pass, one M read per iteration) ----
// Math validated in R13 (passed, rel_err 9.07e-08). RB=8 fixes parallelism:
// 512 CTAs (NN) / 256 CTAs (NP) per iteration instead of 128.
// e = exp(M + v_old); row LSE gives u_new; col partial accumulates e*exp(u_new)
//   = exp(v_old[col]) * exp(M + u_new); combine: v_new = log_b + v_old - log(sum ps).
template<int CPT>
__global__ void k_sink_iter(const float* __restrict__ M, const float* __restrict__ v,
                            float* __restrict__ u, float* __restrict__ ps,
                            int C, int RB, float log_a) {
    int t = threadIdx.x;
    int r0 = blockIdx.y * RB;
    float vv[CPT], part[CPT];
    #pragma unroll
    for (int k = 0; k < CPT; k++) { vv[k] = v[t + (k << 8)]; part[k] = 0.f; }
    for (int r = r0; r < r0 + RB; r++) {
        const float* row = M + (size_t)r * C;
        float e[CPT];
        float s = 0.f;
        #pragma unroll
        for (int k = 0; k < CPT; k++) {
            e[k] = __expf(row[t + (k << 8)] + vv[k]);
            s += e[k];
        }
        float S = blockReduceSumB(s);
        float ur = log_a - logf(S);
        if (t == 0) u[r] = ur;
        float eu = __expf(ur);
        #pragma unroll
        for (int k = 0; k < CPT; k++) part[k] += e[k] * eu;
    }
    #pragma unroll
    for (int k = 0; k < CPT; k++) ps[(size_t)blockIdx.y * C + t + (k << 8)] = part[k];
}

__global__ void k_sink_comb(const float* __restrict__ ps, float* __restrict__ v,
                            int C, int splits, float log_b) {
    int col = blockIdx.x * blockDim.x + threadIdx.x;
    if (col >= C) return;
    float s = 0.f;
    for (int k = 0; k < splits; k++) s += ps[(size_t)k * C + col];
    v[col] = log_b + v[col] - logf(s);
}

// fused plan_p marginals: row sums (rs) + col partials (ps) of exp(M+u+v), one read
template<int CPT>
__global__ void k_pp_marg(const float* __restrict__ M, const float* __restrict__ u,
                          const float* __restrict__ v, float* __restrict__ rs,
                          float* __restrict__ ps, int C, int RB) {
    int t = threadIdx.x;
    int r0 = blockIdx.y * RB;
    float vv[CPT], part[CPT];
    #pragma unroll
    for (int k = 0; k < CPT; k++) { vv[k] = v[t + (k << 8)]; part[k] = 0.f; }
    for (int r = r0; r < r0 + RB; r++) {
        const float* row = M + (size_t)r * C;
        float uu = u[r];
        float e[CPT];
        float s = 0.f;
        #pragma unroll
        for (int k = 0; k < CPT; k++) {
            e[k] = __expf(row[t + (k << 8)] + uu + vv[k]);
            s += e[k];
        }
        float S = blockReduceSumB(s);
        if (t == 0) rs[r] = S;
        #pragma unroll
        for (int k = 0; k < CPT; k++) part[k] += e[k];
    }
    #pragma unroll
    for (int k = 0; k < CPT; k++) ps[(size_t)blockIdx.y * C + t + (k << 8)] = part[k];
}

// fused plan_u: write P = exp(M+u+v), row sums, col partials — one read, one write
template<int CPT>
__global__ void k_plan_marg(const float* __restrict__ M, const float* __restrict__ u,
                            const float* __restrict__ v, float* __restrict__ P,
                            float* __restrict__ rs, float* __restrict__ ps,
                            int C, int RB) {
    int t = threadIdx.x;
    int r0 = blockIdx.y * RB;
    float vv[CPT], part[CPT];
    #pragma unroll
    for (int k = 0; k < CPT; k++) { vv[k] = v[t + (k << 8)]; part[k] = 0.f; }
    for (int r = r0; r < r0 + RB; r++) {
        const float* row = M + (size_t)r * C;
        float* prow = P + (size_t)r * C;
        float uu = u[r];
        float e[CPT];
        float s = 0.f;
        #pragma unroll
        for (int k = 0; k < CPT; k++) {
            e[k] = __expf(row[t + (k << 8)] + uu + vv[k]);
            prow[t + (k << 8)] = e[k];
            s += e[k];
        }
        float S = blockReduceSumB(s);
        if (t == 0) rs[r] = S;
        #pragma unroll
        for (int k = 0; k < CPT; k++) part[k] += e[k];
    }
    #pragma unroll
    for (int k = 0; k < CPT; k++) ps[(size_t)blockIdx.y * C + t + (k << 8)] = part[k];
}

__global__ void k_colsum_comb(const float* __restrict__ part, float* __restrict__ cs,
                              int C, int splits) {
    int col = blockIdx.x * blockDim.x + threadIdx.x;
    if (col >= C) return;
    float s = 0.f;
    for (int k = 0; k < splits; k++) s += part[(size_t)k * C + col];
    cs[col] = s;
}

// ---------------- loss reductions ----------------
__global__ void k_marg(const float* __restrict__ s, int n) {
    float inv = 1.f / (float)n;
    float local = 0.f;
    for (int i = blockIdx.x * blockDim.x + threadIdx.x; i < n; i += gridDim.x * blockDim.x) {
        float d = s[i] - inv; local += d * d;
    }
    float tot = blockReduceSum(local);
    if (threadIdx.x == 0) atomicAdd(&g_acc[0], (double)tot);
}

// sail / exp / imp over the pair cost matrix
__global__ void k_pair_losses(const float* __restrict__ Mp, const float* __restrict__ u,
                              const float* __restrict__ v) {
    float sail = 0.f, expd = 0.f, impd = 0.f;
    const size_t n = (size_t)NP * NP;
    for (size_t idx = (size_t)blockIdx.x * blockDim.x + threadIdx.x; idx < n;
         idx += (size_t)gridDim.x * blockDim.x) {
        int i = (int)(idx >> 11), j = (int)(idx & 2047);
        float mval = Mp[idx];
        float cosv = mval * 0.05f;                 // Mp = 20*cos
        float z = (i == j) ? cosv * 10.f : -cosv * 10.f;
        float x = -z;                              // softplus(-z) = -log_sigmoid(z)
        float sp = (x > 0.f) ? x + log1pf(__expf(-x)) : log1pf(__expf(x));
        sail += sp;
        if (i == j) {
            expd += (1.f - cosv) * 0.5f;
            impd += mval + u[i] + v[j];
        }
    }
    float t;
    t = blockReduceSum(sail); if (threadIdx.x == 0) atomicAdd(&g_acc[1], (double)t);
    t = blockReduceSum(expd); if (threadIdx.x == 0) atomicAdd(&g_acc[2], (double)t);
    t = blockReduceSum(impd); if (threadIdx.x == 0) atomicAdd(&g_acc[3], (double)t);
}

// L_ot = sum( exp(logp_a) * (logp_a - logp_u) )
__global__ void k_ot(const float* __restrict__ Ma, const float* __restrict__ ua,
                     const float* __restrict__ va, const float* __restrict__ Mu,
                     const float* __restrict__ uu, const float* __restrict__ vu) {
    float local = 0.f;
    const size_t n = (size_t)NN * NN;
    for (size_t idx = (size_t)blockIdx.x * blockDim.x + threadIdx.x; idx < n;
         idx += (size_t)gridDim.x * blockDim.x) {
        int i = (int)(idx >> 12), j = (int)(idx & 4095);
        float lpa = Ma[idx] + ua[i] + va[j];
        float lpu = Mu[idx] + uu[i] + vu[j];
        local += __expf(lpa) * (lpa - lpu);
    }
    float tot = blockReduceSum(local);
    if (threadIdx.x == 0) atomicAdd(&g_acc[4], (double)tot);
}

__global__ void k_dot(const float* __restrict__ A, const float* __restrict__ B,
                      size_t n, int slot) {
    float local = 0.f;
    for (size_t i = (size_t)blockIdx.x * blockDim.x + threadIdx.x; i < n;
         i += (size_t)gridDim.x * blockDim.x) local += A[i] * B[i];
    float tot = blockReduceSum(local);
    if (threadIdx.x == 0) atomicAdd(&g_acc[slot], (double)tot);
}

__global__ void k_final(float* out) {
    double Npd = 2048.0;
    double cste = 4096.0 * 4096.0;
    double L = g_acc[0]
             + g_acc[1] / (Npd * Npd)
             + g_acc[2] / Npd
             + (-(g_acc[3]) / Npd - log(Npd))
             + g_acc[4]
             + (g_acc[5] + g_acc[6] - 2.0 * g_acc[7]) / cste
             + (g_acc[8] + g_acc[9] - 2.0 * g_acc[10]);
    out[0] = (float)L;
}

// ---------------- host-side helpers ----------------
static inline float* sym(const void* s) {
    void* p = nullptr;
    cudaGetSymbolAddress(&p, s);
    return (float*)p;
}

// S = split-K factor (K % S == 0 and (K/S) % 8 == 0 required).
static inline void gemm(const float* A, const float* B, float* C,
                        int M, int N, int K, float alpha, bool ta, bool tb, int S = 1) {
    float* out = C;
    if (S > 1) out = sym(g_skw);
    int Kc = K / S;
    dim3 g(N / 128, M / 128, S), b(256);
    if (!ta && !tb)      k_gemm<false, false><<<g, b>>>(A, B, out, M, N, K, Kc, alpha);
    else if (ta && !tb)  k_gemm<true,  false><<<g, b>>>(A, B, out, M, N, K, Kc, alpha);
    else if (!ta && tb)  k_gemm<false, true ><<<g, b>>>(A, B, out, M, N, K, Kc, alpha);
    else                 k_gemm<true,  true ><<<g, b>>>(A, B, out, M, N, K, Kc, alpha);
    if (S > 1) {
        size_t mn = (size_t)M * N;
        int blocks = (int)((mn + 255) / 256);
        if (blocks > 1024) blocks = 1024;
        k_sk_reduce<<<blocks, 256>>>(out, C, mn, S);
    }
}

// fused Sinkhorn: 2 kernels per iteration, M read once per iteration. RB=8.
template<int CPT>
static inline void run_sinkhorn(const float* M, float* u, float* v, int R, int C,
                                float* ps) {
    float log_a = -logf((float)R), log_b = -logf((float)C);
    const int RB = 8;
    int splits = R / RB;
    k_zero_vec<<<(C + 255) / 256, 256>>>(v, C);
    for (int it = 0; it < 10; it++) {
        k_sink_iter<CPT><<<dim3(1, splits), 256>>>(M, v, u, ps, C, RB, log_a);
        k_sink_comb<<<(C + 255) / 256, 256>>>(ps, v, C, splits, log_b);
    }
}

extern "C" void kernel_launch(void* const* d_in, const int* in_sizes, int n_in,
                              void* d_out, int out_size) {
    const float* fXp = (const float*)d_in[0];
    const float* fYp = (const float*)d_in[1];
    const float* X   = (const float*)d_in[2];
    const float* Y   = (const float*)d_in[3];
    const float* fX  = (const float*)d_in[4];
    const float* fY  = (const float*)d_in[5];
    const float* Xan = (const float*)d_in[6];
    const float* Yan = (const float*)d_in[7];
    float* out = (float*)d_out;

    float *pXa = sym(g_Xa), *pYa = sym(g_Ya);
    float *pSxx = sym(g_Sxx), *pSyy = sym(g_Syy), *pSxy = sym(g_Sxy);
    float *pfXp = sym(g_fXp), *pfYp = sym(g_fYp);
    float *pMp = sym(g_Mp);
    float *pfXn = sym(g_fXn), *pfYn = sym(g_fYn);
    float *pMu = sym(g_Mu), *pMa = sym(g_Ma), *pP = sym(g_P);
    float *pXS = sym(g_XS), *pYS = sym(g_YS);
    float *pXn = sym(g_Xn), *pYn = sym(g_Yn);
    float *pXu = sym(g_Xu), *pYu = sym(g_Yu);
    float *pT = sym(g_T);
    float *pCxx = sym(g_Cxx), *pCyy = sym(g_Cyy);
    float *pU1 = sym(g_U1), *pV1 = sym(g_V1);
    float *pFxx = sym(g_Fxx), *pFyy = sym(g_Fyy);
    float *pW1 = sym(g_W1), *pW2 = sym(g_W2), *pW3 = sym(g_W3);
    float *pMA = sym(g_MA);
    float *pu1 = sym(g_u1), *pv1 = sym(g_v1);
    float *pu2 = sym(g_u2), *pv2 = sym(g_v2);
    float *pu3 = sym(g_u3), *pv3 = sym(g_v3);
    float *pps = sym(g_ps);
    float *prsp = sym(g_rsp), *pcsp = sym(g_csp);
    float *pa = sym(g_a), *pb = sym(g_b);

    k_zero_acc<<<1, 32>>>();

    // ---- anchor covariances ----
    k_rownorm<<<NN, 256>>>(Xan, pXa, DX);
    k_rownorm<<<NN, 256>>>(Yan, pYa, DY);
    const float invN = 1.0f / (float)NN;
    gemm(pXa, pXa, pSxx, DX, DX, NN, invN, true, false, 8);
    gemm(pYa, pYa, pSyy, DY, DY, NN, invN, true, false, 8);
    gemm(pXa, pYa, pSxy, DX, DY, NN, invN, true, false, 8);

    // ---- cost matrices (M = cos/eps = 20*cos) ----
    k_rownorm<<<NP, 256>>>(fXp, pfXp, DF);
    k_rownorm<<<NP, 256>>>(fYp, pfYp, DF);
    gemm(pfXp, pfYp, pMp, NP, NP, DF, EPS_INV, false, true);
    k_rownorm<<<NN, 256>>>(fX, pfXn, DF);
    k_rownorm<<<NN, 256>>>(fY, pfYn, DF);
    gemm(pfXn, pfYn, pMu, NN, NN, DF, EPS_INV, false, true);

    // ---- sinkhorns (pairs + latent) ----
    run_sinkhorn<8>(pMp, pu1, pv1, NP, NP, pps);    // 256 CTAs/iter
    run_sinkhorn<16>(pMu, pu2, pv2, NN, NN, pps);   // 512 CTAs/iter

    // ---- plan_p marginals (fused, single M read) + pair losses ----
    k_pp_marg<8><<<dim3(1, NP / 8), 256>>>(pMp, pu1, pv1, prsp, pps, NP, 8);
    k_colsum_comb<<<(NP + 255) / 256, 256>>>(pps, pcsp, NP, NP / 8);
    k_marg<<<(NP + 255) / 256, 256>>>(prsp, NP);
    k_marg<<<(NP + 255) / 256, 256>>>(pcsp, NP);
    k_pair_losses<<<4096, 256>>>(pMp, pu1, pv1);

    // ---- plan_u: materialize P + marginals in one pass ----
    k_plan_marg<16><<<dim3(1, NN / 8), 256>>>(pMu, pu2, pv2, pP, pa, pps, NN, 8);
    k_colsum_comb<<<(NN + 255) / 256, 256>>>(pps, pb, NN, NN / 8);
    k_marg<<<(NN + 255) / 256, 256>>>(pa, NN);
    k_marg<<<(NN + 255) / 256, 256>>>(pb, NN);

    // ---- anchor-space plan ----
    gemm(X, pSxx, pXS, NN, DX, DX, 1.0f, false, false);           // grid 192
    k_metricnorm<<<NN, 256>>>(X, pXS, pXn, DX);
    gemm(Y, pSyy, pYS, NN, DY, DY, 1.0f, false, false, 2);        // 128 -> 256
    k_metricnorm<<<NN, 256>>>(Y, pYS, pYn, DY);
    gemm(pXn, pSxy, pT, NN, DY, DX, 1.0f, false, false, 2);       // 128 -> 256
    gemm(pT, pYn, pMa, NN, NN, DY, EPS_INV, false, true);         // grid 1024
    run_sinkhorn<16>(pMa, pu3, pv3, NN, NN, pps);
    k_ot<<<4096, 256>>>(pMa, pu3, pv3, pMu, pu2, pv2);

    // ---- L_div ----
    gemm(pXn, pXn, pCxx, DX, DX, NN, 1.0f, true, false, 8);
    gemm(pYn, pYn, pCyy, DY, DY, NN, 1.0f, true, false, 8);
    gemm(pCxx, pSxy, pU1, DX, DY, DX, 1.0f, false, false, 6);     // Kc=128
    gemm(pU1, pCyy, pV1, DX, DY, DY, 1.0f, false, false, 8);      // Kc=64
    k_dot<<<1024, 256>>>(pV1, pSxy, (size_t)DX * DY, 5);
    gemm(pfXn, pfXn, pFxx, DF, DF, NN, 1.0f, true, false, 32);    // 4 -> 128
    gemm(pfYn, pfYn, pFyy, DF, DF, NN, 1.0f, true, false, 32);
    k_dot<<<256, 256>>>(pFxx, pFyy, (size_t)DF * DF, 6);
    gemm(pXn, pfXn, pW1, DX, DF, NN, 1.0f, true, false, 16);      // 12 -> 192
    gemm(pfYn, pYn, pW2, DF, DY, NN, 1.0f, true, false, 16);      // 8 -> 128
    gemm(pW1, pW2, pW3, DX, DY, DF, 1.0f, false, false, 8);       // Kc=32
    k_dot<<<1024, 256>>>(pW3, pSxy, (size_t)DX * DY, 7);

    // ---- L_gw (factored; Kx/Ky never materialized) ----
    k_rownorm<<<NN, 256>>>(X, pXu, DX);
    k_rownorm<<<NN, 256>>>(Y, pYu, DY);
    // aKx^2a = || Xu^T diag(a) Xu ||_F^2
    k_rowscale<<<4096, 256>>>(pXu, pa, pXS, DX, (size_t)NN * DX);
    gemm(pXu, pXS, pMA, DX, DX, NN, 1.0f, true, false, 8);
    k_dot<<<1024, 256>>>(pMA, pMA, (size_t)DX * DX, 8);
    // bKy^2b = || Yu^T diag(b) Yu ||_F^2
    k_rowscale<<<4096, 256>>>(pYu, pb, pYS, DY, (size_t)NN * DY);
    gemm(pYu, pYS, pMA, DY, DY, NN, 1.0f, true, false, 8);
    k_dot<<<1024, 256>>>(pMA, pMA, (size_t)DY * DY, 9);
    // cross term = || Xu^T P Yu ||_F^2
    gemm(pP, pYu, pT, NN, DY, NN, 1.0f, false, false, 2);         // 128 -> 256
    gemm(pXu, pT, pMA, DX, DY, NN, 1.0f, true, false, 8);         // 24 -> 192
    k_dot<<<1024, 256>>>(pMA, pMA, (size_t)DX * DY, 10);

    // ---- combine ----
    k_final<<<1, 1>>>(out);
}